// round 8
// baseline (speedup 1.0000x reference)
#include <cuda_runtime.h>

// HakesPQ forward: out[n, m*16:(m+1)*16] = codebooks[m, k*, :]
// k* = argmin_k fl( fl(v2 - fl(2*<v,c_k>)) + |c_k|^2 ), exact fp32 emulation of
// the reference (jax/XLA-CPU): all reductions are sequential fmaf chains over
// d ascending; ties -> lowest k. Arithmetic order is FROZEN (rel_err==0.0).
// fma.rn.f32x2 performs two independent IEEE fp32 RN FMAs -> packing the k=2kp
// (lo lane) and k=2kp+1 (hi lane) chains preserves bitwise semantics per lane.
// N=32768, D=768, M=48, KSUB=16, DSUB=16.

#define N_VECS   32768
#define D_DIM    768
#define M_SUB    48
#define KSUB     16
#define DSUB     16

#define NROWS    32          // rows (vectors) per block
#define NTHREADS 512         // 16 warps; warp w handles m = w, w+16, w+32
#define ROW_PAD  772         // 768+4: lane bank-start = 4*lane mod 32 -> conflict-free LDS.128

#define SV_FLOATS    (NROWS * ROW_PAD)                  // 24704
#define SCB2_FLOAT2  (M_SUB * (KSUB / 2) * DSUB)        // 6144 float2 (k-pair packed codebook)
#define SC2_FLOATS   (M_SUB * KSUB)                     // 768
#define SMEM_BYTES   ((SV_FLOATS + 2 * SCB2_FLOAT2 + SC2_FLOATS) * 4)

// ---- packed f32x2 helpers ----
__device__ __forceinline__ unsigned long long ffma2(unsigned long long a,
                                                    unsigned long long b,
                                                    unsigned long long c) {
    unsigned long long d;
    asm("fma.rn.f32x2 %0, %1, %2, %3;" : "=l"(d) : "l"(a), "l"(b), "l"(c));
    return d;
}
__device__ __forceinline__ unsigned long long pack2(float x) {
    unsigned long long r;
    asm("mov.b64 %0, {%1, %1};" : "=l"(r) : "f"(x));
    return r;
}
__device__ __forceinline__ void unpack2(unsigned long long a, float& lo, float& hi) {
    asm("mov.b64 {%0, %1}, %2;" : "=f"(lo), "=f"(hi) : "l"(a));
}

__global__ void __launch_bounds__(NTHREADS, 1)
pq_kernel(const float* __restrict__ vecs,
          const float* __restrict__ cb,
          float* __restrict__ out)
{
    extern __shared__ float smem[];
    float*  sv   = smem;
    float2* scb2 = (float2*)(smem + SV_FLOATS);
    float*  sc2  = (float*)(scb2 + SCB2_FLOAT2);

    const int tid = threadIdx.x;

    // ---- codebook repack: scb2[(m*8+kp)*16 + d] = (cb[m][2kp][d], cb[m][2kp+1][d]) ----
    for (int i = tid; i < SCB2_FLOAT2; i += NTHREADS) {
        int d  = i & 15;
        int kp = (i >> 4) & 7;
        int m  = i >> 7;
        const float* base = cb + (m * KSUB + 2 * kp) * DSUB + d;
        scb2[i] = make_float2(base[0], base[DSUB]);
    }
    // ---- |c|^2, reference-emulated sequential fma chain ----
    for (int i = tid; i < SC2_FLOATS; i += NTHREADS) {
        const float* c = cb + i * DSUB;
        float s = 0.0f;
        #pragma unroll
        for (int d = 0; d < DSUB; d++) s = fmaf(c[d], c[d], s);
        sc2[i] = s;
    }

    // ---- stage 32-row v tile into shared (fully coalesced) ----
    const long long row0 = (long long)blockIdx.x * NROWS;
    const float4* vin = (const float4*)(vecs + row0 * D_DIM);
    #pragma unroll 4
    for (int i = tid; i < NROWS * (D_DIM / 4); i += NTHREADS) {
        int r  = i / (D_DIM / 4);
        int c4 = i % (D_DIM / 4);
        *(float4*)(sv + r * ROW_PAD + c4 * 4) = vin[i];
    }
    __syncthreads();

    const int warp = tid >> 5;
    const int lane = tid & 31;
    float* myrow = sv + lane * ROW_PAD;

    #pragma unroll 1
    for (int j = 0; j < 3; j++) {
        const int m = warp + j * 16;              // warp-uniform m
        float* myv = myrow + m * DSUB;            // 16B aligned, conflict-free LDS.128

        // v chunk -> 16 registers
        float4 a0 = *(const float4*)(myv + 0);
        float4 a1 = *(const float4*)(myv + 4);
        float4 a2 = *(const float4*)(myv + 8);
        float4 a3 = *(const float4*)(myv + 12);
        float v[16] = { a0.x, a0.y, a0.z, a0.w,
                        a1.x, a1.y, a1.z, a1.w,
                        a2.x, a2.y, a2.z, a2.w,
                        a3.x, a3.y, a3.z, a3.w };

        // v2: sequential scalar fma chain ascending (frozen)
        float v2 = 0.0f;
        #pragma unroll
        for (int d = 0; d < DSUB; d++) v2 = fmaf(v[d], v[d], v2);

        // duplicated-lane v operands for packed chains
        unsigned long long vdd[16];
        #pragma unroll
        for (int d = 0; d < DSUB; d++) vdd[d] = pack2(v[d]);

        const ulonglong2* pcb = (const ulonglong2*)(scb2 + m * (KSUB / 2) * DSUB);
        const float*      c2m = sc2 + m * KSUB;

        float best_t = 3.402823466e38f;
        int   bk     = 0;
        #pragma unroll
        for (int kp = 0; kp < KSUB / 2; ++kp) {
            // 16 float2 (128B) per k-pair chain: 8x LDS.128 broadcast
            const ulonglong2* cw = pcb + kp * 8;
            unsigned long long acc = 0ULL;
            #pragma unroll
            for (int dd = 0; dd < 8; ++dd) {
                ulonglong2 q = cw[dd];               // (d=2dd, d=2dd+1) for both k's
                acc = ffma2(vdd[2 * dd],     q.x, acc);
                acc = ffma2(vdd[2 * dd + 1], q.y, acc);
            }
            float accLo, accHi;
            unpack2(acc, accLo, accHi);
            // frozen elementwise ops, ascending k, strict < (first max wins)
            float t0 = __fadd_rn(__fsub_rn(v2, __fmul_rn(2.0f, accLo)), c2m[2 * kp]);
            if (t0 < best_t) { best_t = t0; bk = 2 * kp; }
            float t1 = __fadd_rn(__fsub_rn(v2, __fmul_rn(2.0f, accHi)), c2m[2 * kp + 1]);
            if (t1 < best_t) { best_t = t1; bk = 2 * kp + 1; }
        }

        // gather winning codeword from global (L1/L2-hot 48KB), stash in sv
        const float4* gk = (const float4*)(cb + (m * KSUB + bk) * DSUB);
        float4 g0 = __ldg(gk + 0);
        float4 g1 = __ldg(gk + 1);
        float4 g2 = __ldg(gk + 2);
        float4 g3 = __ldg(gk + 3);
        *(float4*)(myv + 0)  = g0;
        *(float4*)(myv + 4)  = g1;
        *(float4*)(myv + 8)  = g2;
        *(float4*)(myv + 12) = g3;
    }
    __syncthreads();

    // ---- write tile back, fully coalesced ----
    float4* vout = (float4*)(out + row0 * D_DIM);
    #pragma unroll 4
    for (int i = tid; i < NROWS * (D_DIM / 4); i += NTHREADS) {
        int r  = i / (D_DIM / 4);
        int c4 = i % (D_DIM / 4);
        vout[i] = *(float4*)(sv + r * ROW_PAD + c4 * 4);
    }
}

extern "C" void kernel_launch(void* const* d_in, const int* in_sizes, int n_in,
                              void* d_out, int out_size)
{
    const float* vecs = (const float*)d_in[0];   // (N, 768) f32
    const float* cb   = (const float*)d_in[1];   // (48, 16, 16) f32
    float*       out  = (float*)d_out;           // (N, 768) f32

    cudaFuncSetAttribute(pq_kernel, cudaFuncAttributeMaxDynamicSharedMemorySize, SMEM_BYTES);
    pq_kernel<<<N_VECS / NROWS, NTHREADS, SMEM_BYTES>>>(vecs, cb, out);
}

// round 9
// speedup vs baseline: 1.0068x; 1.0068x over previous
#include <cuda_runtime.h>

// HakesPQ forward: out[n, m*16:(m+1)*16] = codebooks[m, k*, :]
// k* = argmin_k fl( fl(v2 - fl(2*<v,c_k>)) + |c_k|^2 ), exact fp32 emulation of
// the reference (jax/XLA-CPU): all reductions are sequential fmaf chains over
// d ascending; ties -> lowest k. Arithmetic order is FROZEN (rel_err==0.0).
// N=32768, D=768, M=48, KSUB=16, DSUB=16.
//
// R8: occupancy round. M split across blockIdx.y halves (24 m per CTA),
// 16 rows per CTA, 1 task per thread, 384 threads, <=56 regs, ~50KB smem
// -> 3 CTAs/SM (36 warps) instead of 1 CTA (16 warps).

#define N_VECS   32768
#define D_DIM    768
#define M_SUB    48
#define KSUB     16
#define DSUB     16

#define MHALF    24                   // m per CTA
#define CHALF    (MHALF * DSUB)       // 384 v-columns per CTA
#define NROWS    16                   // rows per CTA
#define NTHREADS 384                  // 12 warps, 1 task/thread
#define ROW_PAD  388                  // 384+4: 4*row mod 32 -> conflict-free LDS.128

#define SV_FLOATS   (NROWS * ROW_PAD)          // 6208
#define SCB_FLOATS  (MHALF * KSUB * DSUB)      // 6144
#define SC2_FLOATS  (MHALF * KSUB)             // 384
#define SMEM_BYTES  ((SV_FLOATS + SCB_FLOATS + SC2_FLOATS) * 4)   // ~50.9 KB

__global__ void __launch_bounds__(NTHREADS, 3)
pq_kernel(const float* __restrict__ vecs,
          const float* __restrict__ cb,
          float* __restrict__ out)
{
    extern __shared__ float smem[];
    float* sv  = smem;                 // [NROWS][ROW_PAD] v tile (this CTA's columns)
    float* scb = smem + SV_FLOATS;     // [MHALF][KSUB][DSUB] codebook half
    float* sc2 = scb + SCB_FLOATS;     // [MHALF][KSUB] |c|^2 half

    const int tid = threadIdx.x;
    const int mh  = blockIdx.y;                    // 0 or 1: which m-half
    const float* cb_half = cb + mh * (MHALF * KSUB * DSUB);

    // ---- codebook half into shared (contiguous, coalesced float4) ----
    {
        const float4* src = (const float4*)cb_half;
        float4*       dst = (float4*)scb;
        #pragma unroll
        for (int i = tid; i < SCB_FLOATS / 4; i += NTHREADS) dst[i] = src[i];
    }
    // ---- |c|^2: one (m,k) per thread, frozen sequential fma chain ----
    {
        const float* c = cb_half + tid * DSUB;     // tid < 384 = MHALF*KSUB
        float s = 0.0f;
        #pragma unroll
        for (int d = 0; d < DSUB; d++) s = fmaf(c[d], c[d], s);
        sc2[tid] = s;
    }

    // ---- stage this CTA's 16x384 v sub-tile (coalesced float4) ----
    const long long row0 = (long long)blockIdx.x * NROWS;
    {
        const float4* vin = (const float4*)(vecs + row0 * D_DIM) + mh * (CHALF / 4);
        #pragma unroll
        for (int i = tid; i < NROWS * (CHALF / 4); i += NTHREADS) {
            int r  = i / (CHALF / 4);
            int c4 = i % (CHALF / 4);
            *(float4*)(sv + r * ROW_PAD + c4 * 4) =
                vin[(long long)r * (D_DIM / 4) + c4];
        }
    }
    __syncthreads();

    // ---- one (row, m) task per thread ----
    const int row = tid & (NROWS - 1);     // lane&15: rows 0..15
    const int ml  = tid >> 4;              // 0..23 local m (2 per warp)
    float* myv = sv + row * ROW_PAD + ml * DSUB;   // conflict-free LDS.128

    float4 a0 = *(const float4*)(myv + 0);
    float4 a1 = *(const float4*)(myv + 4);
    float4 a2 = *(const float4*)(myv + 8);
    float4 a3 = *(const float4*)(myv + 12);
    float v[16] = { a0.x, a0.y, a0.z, a0.w,
                    a1.x, a1.y, a1.z, a1.w,
                    a2.x, a2.y, a2.z, a2.w,
                    a3.x, a3.y, a3.z, a3.w };

    // v2: frozen sequential chain ascending
    float v2 = 0.0f;
    #pragma unroll
    for (int d = 0; d < DSUB; d++) v2 = fmaf(v[d], v[d], v2);

    const float* cm  = scb + ml * (KSUB * DSUB);   // uniform per half-warp
    const float* c2m = sc2 + ml * KSUB;

    float best_t = 3.402823466e38f;
    int   bk     = 0;
    #pragma unroll
    for (int k = 0; k < KSUB; ++k) {
        const float* ck = cm + k * DSUB;
        float4 c0 = *(const float4*)(ck + 0);
        float4 c1 = *(const float4*)(ck + 4);
        float4 c2 = *(const float4*)(ck + 8);
        float4 c3 = *(const float4*)(ck + 12);
        float acc = 0.0f;                          // frozen ascending chain
        acc = fmaf(v[0],  c0.x, acc);
        acc = fmaf(v[1],  c0.y, acc);
        acc = fmaf(v[2],  c0.z, acc);
        acc = fmaf(v[3],  c0.w, acc);
        acc = fmaf(v[4],  c1.x, acc);
        acc = fmaf(v[5],  c1.y, acc);
        acc = fmaf(v[6],  c1.z, acc);
        acc = fmaf(v[7],  c1.w, acc);
        acc = fmaf(v[8],  c2.x, acc);
        acc = fmaf(v[9],  c2.y, acc);
        acc = fmaf(v[10], c2.z, acc);
        acc = fmaf(v[11], c2.w, acc);
        acc = fmaf(v[12], c3.x, acc);
        acc = fmaf(v[13], c3.y, acc);
        acc = fmaf(v[14], c3.z, acc);
        acc = fmaf(v[15], c3.w, acc);
        // frozen elementwise ops, RN at each step; strict < -> first max wins
        float t = __fadd_rn(__fsub_rn(v2, __fmul_rn(2.0f, acc)), c2m[k]);
        if (t < best_t) { best_t = t; bk = k; }
    }

    // winner gather (per-thread bk) -> overwrite own dead v region in shared
    {
        const float4* gk = (const float4*)(cm + bk * DSUB);
        float4 g0 = gk[0], g1 = gk[1], g2 = gk[2], g3 = gk[3];
        *(float4*)(myv + 0)  = g0;
        *(float4*)(myv + 4)  = g1;
        *(float4*)(myv + 8)  = g2;
        *(float4*)(myv + 12) = g3;
    }
    __syncthreads();

    // ---- write this CTA's columns back, fully coalesced ----
    {
        float4* vout = (float4*)(out + row0 * D_DIM) + mh * (CHALF / 4);
        #pragma unroll
        for (int i = tid; i < NROWS * (CHALF / 4); i += NTHREADS) {
            int r  = i / (CHALF / 4);
            int c4 = i % (CHALF / 4);
            vout[(long long)r * (D_DIM / 4) + c4] =
                *(float4*)(sv + r * ROW_PAD + c4 * 4);
        }
    }
}

extern "C" void kernel_launch(void* const* d_in, const int* in_sizes, int n_in,
                              void* d_out, int out_size)
{
    const float* vecs = (const float*)d_in[0];   // (N, 768) f32
    const float* cb   = (const float*)d_in[1];   // (48, 16, 16) f32
    float*       out  = (float*)d_out;           // (N, 768) f32

    cudaFuncSetAttribute(pq_kernel, cudaFuncAttributeMaxDynamicSharedMemorySize, SMEM_BYTES);
    dim3 grid(N_VECS / NROWS, 2);
    pq_kernel<<<grid, NTHREADS, SMEM_BYTES>>>(vecs, cb, out);
}